// round 14
// baseline (speedup 1.0000x reference)
#include <cuda_runtime.h>
#include <cuda_fp16.h>
#include <math.h>
#include <cstdint>

// Problem dims (compile-time)
static constexpr int Bsz = 16384;
static constexpr int Dd  = 768;
static constexpr int Kk  = 4;
static constexpr int H1  = 512;
static constexpr int H2  = 256;
static constexpr int KD  = Kk * Dd;        // 3072
static constexpr int NC  = KD + Dd;        // 3840 combined head width

// Scratch (device globals: allocation-free per harness rules)
__device__ float  g_logits[Bsz * Dd];      // fp32 (softmax input precision)
__device__ __half g_wflath[Bsz * KD];      // fp16 wflat scratch
__device__ __half g_embh[Bsz * Dd];
__device__ __half g_h1h[Bsz * H1];
__device__ __half g_h2h[Bsz * H2];
__device__ __half g_W1h[Dd * H1];
__device__ __half g_W2h[H1 * H2];
__device__ __half g_Wch[H2 * NC];          // [Wd | Wa] fp16, row stride NC

__device__ __forceinline__ uint32_t smem_u32(const void* p) {
    uint32_t a;
    asm("{ .reg .u64 t; cvta.to.shared.u64 t, %1; cvt.u32.u64 %0, t; }"
        : "=r"(a) : "l"(p));
    return a;
}

__device__ __forceinline__ void cp_async16(uint32_t dst, const void* src) {
    asm volatile("cp.async.cg.shared.global [%0], [%1], 16;"
                 :: "r"(dst), "l"(src) : "memory");
}
#define CP_COMMIT() asm volatile("cp.async.commit_group;" ::: "memory")
#define CP_WAIT(n)  asm volatile("cp.async.wait_group %0;" :: "n"(n) : "memory")

// ===========================================================================
// FP16 mma GEMM core, occupancy-optimized: BM=64, BN=128, BK=32.
// 256 threads = 8 warps in 2x4 grid, warp tile 32x32 (acc 32 regs).
// 3 CTAs/SM (24 warps) to cover ldmatrix->mma latency; tensor pipe was 42%
// busy at 16 warps/SM with the old 64x32 warp tile.
// HEADS=false: single OutT output C[M,N]+bias.
// HEADS=true : block cols < KD -> fp16 wflath (stride KD); cols >= KD ->
//              fp32 logits (stride Dd); bias from bias/bias2.
// ===========================================================================
#define BM 64
#define BN 128
#define BKt 32

static constexpr int AS_STRIDE = 40;    // halves, conflict-free ldmatrix phases
static constexpr int BS_STRIDE = 136;
static constexpr int AS_ELEMS  = BM * AS_STRIDE;   // 2560 halves
static constexpr int BS_ELEMS  = BKt * BS_STRIDE;  // 4352 halves
static constexpr int NSTAGE    = 3;
static constexpr int GEMM_SMEM_BYTES = NSTAGE * (AS_ELEMS + BS_ELEMS) * 2; // 41472

template <bool HEADS, typename OutT>
__global__ __launch_bounds__(256, 3) void mma_gemm(
    const __half* __restrict__ A, const __half* __restrict__ B,
    const float* __restrict__ bias, OutT* __restrict__ C,
    const float* __restrict__ bias2,          // HEADS: ba
    __half* __restrict__ Cw,                  // HEADS: wflath
    float* __restrict__ Cl,                   // HEADS: logits
    int M, int N, int Kdim)
{
    extern __shared__ __half hsm[];
    const uint32_t aBase = smem_u32(hsm);
    const uint32_t bBase = aBase + NSTAGE * AS_ELEMS * 2;

    const int tid  = threadIdx.x;
    const int lane = tid & 31;
    const int w    = tid >> 5;
    const int wm   = w >> 2;          // 0..1 (32-row slab)
    const int wn   = w & 3;           // 0..3 (32-col slab)
    const int gid  = lane >> 2;       // 0..7
    const int tig  = lane & 3;        // 0..3

    const int m0 = blockIdx.y * BM;
    const int n0 = blockIdx.x * BN;

    float acc[2][4][4];
    #pragma unroll
    for (int i = 0; i < 2; i++)
        #pragma unroll
        for (int j = 0; j < 4; j++)
            #pragma unroll
            for (int r = 0; r < 4; r++) acc[i][j][r] = 0.f;

    const int nch = Kdim / BKt;

    // stage chunk kc into stage buffer s (A: 256 segs, B: 512 segs of 16B)
    auto stage = [&](int kc, int s) {
        const uint32_t aB = aBase + s * AS_ELEMS * 2;
        const uint32_t bB = bBase + s * BS_ELEMS * 2;
        const int k0 = kc * BKt;
        {
            int ar = tid >> 2, as = tid & 3;
            cp_async16(aB + (ar * AS_STRIDE + as * 8) * 2,
                       A + (size_t)(m0 + ar) * Kdim + k0 + as * 8);
        }
        #pragma unroll
        for (int it = 0; it < 2; it++) {
            int sid = tid + it * 256;
            int br = sid >> 4, bs = sid & 15;
            cp_async16(bB + (br * BS_STRIDE + bs * 8) * 2,
                       B + (size_t)(k0 + br) * N + n0 + bs * 8);
        }
    };

    stage(0, 0); CP_COMMIT();
    stage(1, 1); CP_COMMIT();

    for (int kc = 0; kc < nch; kc++) {
        const int cur = kc % NSTAGE;
        if (kc < nch - 1) { CP_WAIT(1); } else { CP_WAIT(0); }
        __syncthreads();
        if (kc + 2 < nch) { stage(kc + 2, (kc + 2) % NSTAGE); CP_COMMIT(); }

        const uint32_t aCur = aBase + cur * AS_ELEMS * 2;
        const uint32_t bCur = bBase + cur * BS_ELEMS * 2;

        #pragma unroll
        for (int ks = 0; ks < 2; ks++) {
            const int kb = ks * 16;
            // A fragments: 2 m-tiles via ldmatrix.x4
            uint32_t af[2][4];
            #pragma unroll
            for (int mi = 0; mi < 2; mi++) {
                const int r = wm * 32 + mi * 16;
                uint32_t addr = aCur
                    + (uint32_t)(r + (lane & 15)) * (AS_STRIDE * 2)
                    + kb * 2 + (lane >> 4) * 16;
                asm volatile(
                    "ldmatrix.sync.aligned.m8n8.x4.shared.b16 {%0,%1,%2,%3}, [%4];"
                    : "=r"(af[mi][0]), "=r"(af[mi][1]),
                      "=r"(af[mi][2]), "=r"(af[mi][3]) : "r"(addr));
            }
            // B fragments: 2 ldmatrix.x4.trans cover 4 n-tiles
            uint32_t bf[4][2];
            #pragma unroll
            for (int nj = 0; nj < 2; nj++) {
                const int c = wn * 32 + nj * 16;
                uint32_t addr = bCur
                    + (uint32_t)(kb + ((lane >> 3) & 1) * 8 + (lane & 7)) * (BS_STRIDE * 2)
                    + (uint32_t)(c + (lane >> 4) * 8) * 2;
                asm volatile(
                    "ldmatrix.sync.aligned.m8n8.x4.trans.shared.b16 {%0,%1,%2,%3}, [%4];"
                    : "=r"(bf[nj * 2][0]), "=r"(bf[nj * 2][1]),
                      "=r"(bf[nj * 2 + 1][0]), "=r"(bf[nj * 2 + 1][1]) : "r"(addr));
            }
            #pragma unroll
            for (int mi = 0; mi < 2; mi++)
                #pragma unroll
                for (int ni = 0; ni < 4; ni++) {
                    asm volatile(
                        "mma.sync.aligned.m16n8k16.row.col.f32.f16.f16.f32 "
                        "{%0,%1,%2,%3}, {%4,%5,%6,%7}, {%8,%9}, {%0,%1,%2,%3};"
                        : "+f"(acc[mi][ni][0]), "+f"(acc[mi][ni][1]),
                          "+f"(acc[mi][ni][2]), "+f"(acc[mi][ni][3])
                        : "r"(af[mi][0]), "r"(af[mi][1]), "r"(af[mi][2]), "r"(af[mi][3]),
                          "r"(bf[ni][0]), "r"(bf[ni][1]));
                }
        }
    }

    // Epilogue
    if constexpr (HEADS) {
        const bool isW = (n0 < KD);   // whole block is one region (KD % BN == 0)
        #pragma unroll
        for (int mi = 0; mi < 2; mi++) {
            const int r0 = m0 + wm * 32 + mi * 16 + gid;
            #pragma unroll
            for (int ni = 0; ni < 4; ni++) {
                const int c = n0 + wn * 32 + ni * 8 + tig * 2;
                if (isW) {
                    const float2 bv = *(const float2*)(bias + c);
                    *(__half2*)(Cw + (size_t)r0 * KD + c) =
                        __floats2half2_rn(acc[mi][ni][0] + bv.x, acc[mi][ni][1] + bv.y);
                    *(__half2*)(Cw + (size_t)(r0 + 8) * KD + c) =
                        __floats2half2_rn(acc[mi][ni][2] + bv.x, acc[mi][ni][3] + bv.y);
                } else {
                    const int cl = c - KD;
                    const float2 bv = *(const float2*)(bias2 + cl);
                    *(float2*)(Cl + (size_t)r0 * Dd + cl) =
                        make_float2(acc[mi][ni][0] + bv.x, acc[mi][ni][1] + bv.y);
                    *(float2*)(Cl + (size_t)(r0 + 8) * Dd + cl) =
                        make_float2(acc[mi][ni][2] + bv.x, acc[mi][ni][3] + bv.y);
                }
            }
        }
    } else {
        #pragma unroll
        for (int mi = 0; mi < 2; mi++) {
            const int r0 = m0 + wm * 32 + mi * 16 + gid;
            #pragma unroll
            for (int ni = 0; ni < 4; ni++) {
                const int c = n0 + wn * 32 + ni * 8 + tig * 2;
                const float2 bv = *(const float2*)(bias + c);
                float x0 = acc[mi][ni][0] + bv.x;
                float y0 = acc[mi][ni][1] + bv.y;
                float x1 = acc[mi][ni][2] + bv.x;
                float y1 = acc[mi][ni][3] + bv.y;
                *(__half2*)((__half*)C + (size_t)r0 * N + c)       = __floats2half2_rn(x0, y0);
                *(__half2*)((__half*)C + (size_t)(r0 + 8) * N + c) = __floats2half2_rn(x1, y1);
            }
        }
    }
}

// ===========================================================================
// Converters: one 3-segment contiguous kernel + strided for Wch
// ===========================================================================
__global__ void cvt3_k(const float* __restrict__ s0, __half* __restrict__ d0, int n0,
                       const float* __restrict__ s1, __half* __restrict__ d1, int n1,
                       const float* __restrict__ s2, __half* __restrict__ d2, int n2)
{
    int q = blockIdx.x * blockDim.x + threadIdx.x;   // quad index
    int i = q * 4;
    const float* s; __half* d; int off;
    if (i < n0)           { s = s0; d = d0; off = i; }
    else if (i < n0 + n1) { s = s1; d = d1; off = i - n0; }
    else if (i < n0 + n1 + n2) { s = s2; d = d2; off = i - n0 - n1; }
    else return;
    float4 v = *(const float4*)(s + off);
    __half2* p = (__half2*)(d + off);
    p[0] = __floats2half2_rn(v.x, v.y);
    p[1] = __floats2half2_rn(v.z, v.w);
}

__global__ void f32_to_f16_strided(const float* __restrict__ s, __half* __restrict__ d,
                                   int srcCols, int dstStride, int colOff, int n)
{
    int i = (blockIdx.x * blockDim.x + threadIdx.x) * 4;
    if (i < n) {
        int r = i / srcCols, c = i % srcCols;   // srcCols % 4 == 0
        float4 v = *(const float4*)(s + i);
        __half2* p = (__half2*)(d + (size_t)r * dstStride + colOff + c);
        p[0] = __floats2half2_rn(v.x, v.y);
        p[1] = __floats2half2_rn(v.z, v.w);
    }
}

// ===========================================================================
// Block reduction (for LN)
// ===========================================================================
__device__ __forceinline__ float blockSumN(float v, float* red, int nw) {
    #pragma unroll
    for (int o = 16; o > 0; o >>= 1) v += __shfl_down_sync(0xffffffffu, v, o);
    const int lane = threadIdx.x & 31, w = threadIdx.x >> 5;
    if (lane == 0) red[w] = v;
    __syncthreads();
    if (w == 0) {
        v = (lane < nw) ? red[lane] : 0.f;
        #pragma unroll
        for (int o = 4; o > 0; o >>= 1) v += __shfl_down_sync(0xffffffffu, v, o);
        if (lane == 0) red[0] = v;
    }
    __syncthreads();
    float out = red[0];
    __syncthreads();
    return out;
}

// ===========================================================================
// One-pass LayerNorm + ReLU, in-place on fp16 (stats in fp32).
// ===========================================================================
__global__ void ln_relu_h(__half* __restrict__ x, const float* __restrict__ g,
                          const float* __restrict__ be)
{
    __shared__ float red[8];
    const int H = blockDim.x * 4;
    const int nw = blockDim.x >> 5;
    __half2* xp = (__half2*)(x + (size_t)blockIdx.x * H);
    __half2 a = xp[threadIdx.x * 2];
    __half2 b = xp[threadIdx.x * 2 + 1];
    float2 va = __half22float2(a);
    float2 vb = __half22float2(b);

    float s  = va.x + va.y + vb.x + vb.y;
    float s2 = va.x * va.x + va.y * va.y + vb.x * vb.x + vb.y * vb.y;
    s  = blockSumN(s, red, nw);
    s2 = blockSumN(s2, red, nw);
    const float mu  = s / H;
    const float var = s2 / H - mu * mu;
    const float rs  = rsqrtf(var + 1e-5f);

    float4 gg = ((const float4*)g)[threadIdx.x];
    float4 bbv = ((const float4*)be)[threadIdx.x];
    float o0 = fmaxf((va.x - mu) * rs * gg.x + bbv.x, 0.f);
    float o1 = fmaxf((va.y - mu) * rs * gg.y + bbv.y, 0.f);
    float o2 = fmaxf((vb.x - mu) * rs * gg.z + bbv.z, 0.f);
    float o3 = fmaxf((vb.y - mu) * rs * gg.w + bbv.w, 0.f);
    xp[threadIdx.x * 2]     = __floats2half2_rn(o0, o1);
    xp[threadIdx.x * 2 + 1] = __floats2half2_rn(o2, o3);
}

// ===========================================================================
// Warp-per-row epilogue: softmax(fp32 logits) -> attn; W = fp16 wflat * attn;
// Gram-Schmidt K=4; writes W_ortho [B,K,D] + attn [B,D]. No __syncthreads.
// ===========================================================================
__device__ __forceinline__ float warpSum(float v) {
    #pragma unroll
    for (int o = 16; o > 0; o >>= 1) v += __shfl_xor_sync(0xffffffffu, v, o);
    return v;
}
__device__ __forceinline__ float warpMax(float v) {
    #pragma unroll
    for (int o = 16; o > 0; o >>= 1) v = fmaxf(v, __shfl_xor_sync(0xffffffffu, v, o));
    return v;
}

__global__ void epilogue_warp(const __half* __restrict__ wflath,
                              const float* __restrict__ logits,
                              float* __restrict__ out)
{
    const int row  = blockIdx.x * 4 + (threadIdx.x >> 5);
    const int lane = threadIdx.x & 31;
    constexpr int J = Dd / 32;  // 24
    const float* lrow = logits + (size_t)row * Dd;
    const __half* wrow = wflath + (size_t)row * KD;

    // softmax over fp32 logits
    float l[J];
    float m = -INFINITY;
    #pragma unroll
    for (int j = 0; j < J; j++) {
        l[j] = lrow[lane + j * 32];
        m = fmaxf(m, l[j]);
    }
    m = warpMax(m);
    float s = 0.f;
    #pragma unroll
    for (int j = 0; j < J; j++) { l[j] = expf(l[j] - m); s += l[j]; }
    s = warpSum(s);
    const float inv_s = 1.f / s;
    float* out_attn = out + (size_t)Bsz * KD;
    #pragma unroll
    for (int j = 0; j < J; j++) {
        l[j] *= inv_s;                       // l[] now holds attn
        out_attn[(size_t)row * Dd + lane + j * 32] = l[j];
    }

    // load fp16 W rows, modulate
    float wv[Kk][J];
    #pragma unroll
    for (int k = 0; k < Kk; k++)
        #pragma unroll
        for (int j = 0; j < J; j++)
            wv[k][j] = __half2float(wrow[k * Dd + lane + j * 32]) * l[j];

    // Gram-Schmidt
    #pragma unroll
    for (int k = 0; k < Kk; k++) {
        #pragma unroll
        for (int p = 0; p < k; p++) {
            float d = 0.f;
            #pragma unroll
            for (int j = 0; j < J; j++) d += wv[k][j] * wv[p][j];
            d = warpSum(d);
            #pragma unroll
            for (int j = 0; j < J; j++) wv[k][j] -= d * wv[p][j];
        }
        float n2 = 0.f;
        #pragma unroll
        for (int j = 0; j < J; j++) n2 += wv[k][j] * wv[k][j];
        n2 = warpSum(n2);
        const float inv = 1.f / fmaxf(sqrtf(n2), 1e-12f);
        #pragma unroll
        for (int j = 0; j < J; j++) {
            wv[k][j] *= inv;
            out[(size_t)row * KD + k * Dd + lane + j * 32] = wv[k][j];
        }
    }
}

// ===========================================================================
extern "C" void kernel_launch(void* const* d_in, const int* in_sizes, int n_in,
                              void* d_out, int out_size)
{
    const float* emb = (const float*)d_in[0];
    const float* W1  = (const float*)d_in[1];
    const float* b1  = (const float*)d_in[2];
    const float* g1  = (const float*)d_in[3];
    const float* be1 = (const float*)d_in[4];
    const float* W2  = (const float*)d_in[5];
    const float* b2  = (const float*)d_in[6];
    const float* g2  = (const float*)d_in[7];
    const float* be2 = (const float*)d_in[8];
    const float* Wd  = (const float*)d_in[9];
    const float* bd  = (const float*)d_in[10];
    const float* Wa  = (const float*)d_in[11];
    const float* ba  = (const float*)d_in[12];
    float* out = (float*)d_out;

    float *logits;
    __half *wflath, *embh, *h1h, *h2h, *W1h, *W2h, *Wch;
    cudaGetSymbolAddress((void**)&logits, g_logits);
    cudaGetSymbolAddress((void**)&wflath, g_wflath);
    cudaGetSymbolAddress((void**)&embh, g_embh);
    cudaGetSymbolAddress((void**)&h1h, g_h1h);
    cudaGetSymbolAddress((void**)&h2h, g_h2h);
    cudaGetSymbolAddress((void**)&W1h, g_W1h);
    cudaGetSymbolAddress((void**)&W2h, g_W2h);
    cudaGetSymbolAddress((void**)&Wch, g_Wch);

    cudaFuncSetAttribute((const void*)mma_gemm<false, __half>,
                         cudaFuncAttributeMaxDynamicSharedMemorySize, GEMM_SMEM_BYTES);
    cudaFuncSetAttribute((const void*)mma_gemm<true, __half>,
                         cudaFuncAttributeMaxDynamicSharedMemorySize, GEMM_SMEM_BYTES);

    // Converts: emb + W1 + W2 in one kernel; Wd/Wa into combined Wch
    {
        int n0 = Bsz * Dd, n1 = Dd * H1, n2 = H1 * H2;
        int q = (n0 + n1 + n2) / 4;
        cvt3_k<<<(q + 255) / 256, 256>>>(emb, embh, n0, W1, W1h, n1, W2, W2h, n2);
    }
    f32_to_f16_strided<<<(H2 * KD / 4 + 255) / 256, 256>>>(Wd, Wch, KD, NC, 0,  H2 * KD);
    f32_to_f16_strided<<<(H2 * Dd / 4 + 255) / 256, 256>>>(Wa, Wch, Dd, NC, KD, H2 * Dd);

    // Layer 1: fp16 output directly, LN in-place on fp16
    mma_gemm<false, __half><<<dim3(H1 / BN, Bsz / BM), 256, GEMM_SMEM_BYTES>>>(
        embh, W1h, b1, h1h, nullptr, nullptr, nullptr, Bsz, H1, Dd);
    ln_relu_h<<<Bsz, H1 / 4>>>(h1h, g1, be1);
    // Layer 2
    mma_gemm<false, __half><<<dim3(H2 / BN, Bsz / BM), 256, GEMM_SMEM_BYTES>>>(
        h1h, W2h, b2, h2h, nullptr, nullptr, nullptr, Bsz, H2, H1);
    ln_relu_h<<<Bsz, H2 / 4>>>(h2h, g2, be2);
    // Merged heads with mixed store: wflat -> fp16, logits -> fp32
    mma_gemm<true, __half><<<dim3(NC / BN, Bsz / BM), 256, GEMM_SMEM_BYTES>>>(
        h2h, Wch, bd, nullptr, ba, wflath, logits, Bsz, NC, H2);
    // softmax + modulate + Gram-Schmidt (warp per row)
    epilogue_warp<<<Bsz / 4, 128>>>(wflath, logits, out);
}

// round 15
// speedup vs baseline: 1.0556x; 1.0556x over previous
#include <cuda_runtime.h>
#include <cuda_fp16.h>
#include <math.h>
#include <cstdint>

// Problem dims (compile-time)
static constexpr int Bsz = 16384;
static constexpr int Dd  = 768;
static constexpr int Kk  = 4;
static constexpr int H1  = 512;
static constexpr int H2  = 256;
static constexpr int KD  = Kk * Dd;        // 3072
static constexpr int NC  = KD + Dd;        // 3840 combined head width

// Scratch (device globals: allocation-free per harness rules)
__device__ float  g_logits[Bsz * Dd];      // fp32 (softmax input precision)
__device__ __half g_wflath[Bsz * KD];      // fp16 wflat scratch
__device__ __half g_embh[Bsz * Dd];
__device__ __half g_h1h[Bsz * H1];
__device__ __half g_h2h[Bsz * H2];
__device__ __half g_W1h[Dd * H1];
__device__ __half g_W2h[H1 * H2];
__device__ __half g_Wch[H2 * NC];          // [Wd | Wa] fp16, row stride NC

__device__ __forceinline__ uint32_t smem_u32(const void* p) {
    uint32_t a;
    asm("{ .reg .u64 t; cvta.to.shared.u64 t, %1; cvt.u32.u64 %0, t; }"
        : "=r"(a) : "l"(p));
    return a;
}

__device__ __forceinline__ void cp_async16(uint32_t dst, const void* src) {
    asm volatile("cp.async.cg.shared.global [%0], [%1], 16;"
                 :: "r"(dst), "l"(src) : "memory");
}
#define CP_COMMIT() asm volatile("cp.async.commit_group;" ::: "memory")
#define CP_WAIT(n)  asm volatile("cp.async.wait_group %0;" :: "n"(n) : "memory")

// ===========================================================================
// FP16 mma GEMM core: fp16 gmem -> cp.async (3-stage) -> fp16 smem
// -> ldmatrix -> m16n8k16 (fp32 accum). BN=128, BK=32, 256 threads.
// BMv=128: warp tile 64x32 (R13-best, 2 CTAs/SM) — used for GEMM1 + heads.
// BMv=64 : warp tile 32x32 (3 CTAs/SM) — used for GEMM2 (wave fill).
// HEADS=true: block cols < KD -> fp16 wflath (stride KD); cols >= KD ->
//             fp32 logits (stride Dd); bias from bias/bias2.
// ===========================================================================
#define BN 128
#define BKt 32

static constexpr int AS_STRIDE = 40;    // halves, conflict-free ldmatrix phases
static constexpr int BS_STRIDE = 136;
static constexpr int BS_ELEMS  = BKt * BS_STRIDE;  // 4352 halves
static constexpr int NSTAGE    = 3;
template <int BMv> struct GemmCfg {
    static constexpr int AS_ELEMS = BMv * AS_STRIDE;
    static constexpr int SMEM = NSTAGE * (AS_ELEMS + BS_ELEMS) * 2;
};
// BM=128: 56832 B (2 CTAs/SM) ; BM=64: 41472 B (3 CTAs/SM)

template <int BMv, bool HEADS>
__global__ __launch_bounds__(256, (BMv == 128) ? 2 : 3) void mma_gemm(
    const __half* __restrict__ A, const __half* __restrict__ B,
    const float* __restrict__ bias, __half* __restrict__ C,
    const float* __restrict__ bias2,          // HEADS: ba
    __half* __restrict__ Cw,                  // HEADS: wflath
    float* __restrict__ Cl,                   // HEADS: logits
    int M, int N, int Kdim)
{
    constexpr int AS_ELEMS = GemmCfg<BMv>::AS_ELEMS;
    constexpr int MT = BMv / 32;              // m-tiles per warp (4 or 2)
    constexpr int MSLAB = BMv / 2;            // rows per wm slab

    extern __shared__ __half hsm[];
    const uint32_t aBase = smem_u32(hsm);
    const uint32_t bBase = aBase + NSTAGE * AS_ELEMS * 2;

    const int tid  = threadIdx.x;
    const int lane = tid & 31;
    const int w    = tid >> 5;
    const int wm   = w >> 2;          // 0..1
    const int wn   = w & 3;           // 0..3
    const int gid  = lane >> 2;       // 0..7
    const int tig  = lane & 3;        // 0..3

    const int m0 = blockIdx.y * BMv;
    const int n0 = blockIdx.x * BN;

    float acc[MT][4][4];
    #pragma unroll
    for (int i = 0; i < MT; i++)
        #pragma unroll
        for (int j = 0; j < 4; j++)
            #pragma unroll
            for (int r = 0; r < 4; r++) acc[i][j][r] = 0.f;

    const int nch = Kdim / BKt;

    auto stage = [&](int kc, int s) {
        const uint32_t aB = aBase + s * AS_ELEMS * 2;
        const uint32_t bB = bBase + s * BS_ELEMS * 2;
        const int k0 = kc * BKt;
        #pragma unroll
        for (int it = 0; it < BMv / 64; it++) {       // A: BMv*4 segs
            int sid = tid + it * 256;
            int ar = sid >> 2, as = sid & 3;
            cp_async16(aB + (ar * AS_STRIDE + as * 8) * 2,
                       A + (size_t)(m0 + ar) * Kdim + k0 + as * 8);
        }
        #pragma unroll
        for (int it = 0; it < 2; it++) {              // B: 512 segs
            int sid = tid + it * 256;
            int br = sid >> 4, bs = sid & 15;
            cp_async16(bB + (br * BS_STRIDE + bs * 8) * 2,
                       B + (size_t)(k0 + br) * N + n0 + bs * 8);
        }
    };

    stage(0, 0); CP_COMMIT();
    stage(1, 1); CP_COMMIT();

    for (int kc = 0; kc < nch; kc++) {
        const int cur = kc % NSTAGE;
        if (kc < nch - 1) { CP_WAIT(1); } else { CP_WAIT(0); }
        __syncthreads();
        if (kc + 2 < nch) { stage(kc + 2, (kc + 2) % NSTAGE); CP_COMMIT(); }

        const uint32_t aCur = aBase + cur * AS_ELEMS * 2;
        const uint32_t bCur = bBase + cur * BS_ELEMS * 2;

        #pragma unroll
        for (int ks = 0; ks < 2; ks++) {
            const int kb = ks * 16;
            uint32_t af[MT][4];
            #pragma unroll
            for (int mi = 0; mi < MT; mi++) {
                const int r = wm * MSLAB + mi * 16;
                uint32_t addr = aCur
                    + (uint32_t)(r + (lane & 15)) * (AS_STRIDE * 2)
                    + kb * 2 + (lane >> 4) * 16;
                asm volatile(
                    "ldmatrix.sync.aligned.m8n8.x4.shared.b16 {%0,%1,%2,%3}, [%4];"
                    : "=r"(af[mi][0]), "=r"(af[mi][1]),
                      "=r"(af[mi][2]), "=r"(af[mi][3]) : "r"(addr));
            }
            uint32_t bf[4][2];
            #pragma unroll
            for (int nj = 0; nj < 2; nj++) {
                const int c = wn * 32 + nj * 16;
                uint32_t addr = bCur
                    + (uint32_t)(kb + ((lane >> 3) & 1) * 8 + (lane & 7)) * (BS_STRIDE * 2)
                    + (uint32_t)(c + (lane >> 4) * 8) * 2;
                asm volatile(
                    "ldmatrix.sync.aligned.m8n8.x4.trans.shared.b16 {%0,%1,%2,%3}, [%4];"
                    : "=r"(bf[nj * 2][0]), "=r"(bf[nj * 2][1]),
                      "=r"(bf[nj * 2 + 1][0]), "=r"(bf[nj * 2 + 1][1]) : "r"(addr));
            }
            #pragma unroll
            for (int mi = 0; mi < MT; mi++)
                #pragma unroll
                for (int ni = 0; ni < 4; ni++) {
                    asm volatile(
                        "mma.sync.aligned.m16n8k16.row.col.f32.f16.f16.f32 "
                        "{%0,%1,%2,%3}, {%4,%5,%6,%7}, {%8,%9}, {%0,%1,%2,%3};"
                        : "+f"(acc[mi][ni][0]), "+f"(acc[mi][ni][1]),
                          "+f"(acc[mi][ni][2]), "+f"(acc[mi][ni][3])
                        : "r"(af[mi][0]), "r"(af[mi][1]), "r"(af[mi][2]), "r"(af[mi][3]),
                          "r"(bf[ni][0]), "r"(bf[ni][1]));
                }
        }
    }

    // Epilogue
    if constexpr (HEADS) {
        const bool isW = (n0 < KD);   // whole block is one region (KD % BN == 0)
        #pragma unroll
        for (int mi = 0; mi < MT; mi++) {
            const int r0 = m0 + wm * MSLAB + mi * 16 + gid;
            #pragma unroll
            for (int ni = 0; ni < 4; ni++) {
                const int c = n0 + wn * 32 + ni * 8 + tig * 2;
                if (isW) {
                    const float2 bv = *(const float2*)(bias + c);
                    *(__half2*)(Cw + (size_t)r0 * KD + c) =
                        __floats2half2_rn(acc[mi][ni][0] + bv.x, acc[mi][ni][1] + bv.y);
                    *(__half2*)(Cw + (size_t)(r0 + 8) * KD + c) =
                        __floats2half2_rn(acc[mi][ni][2] + bv.x, acc[mi][ni][3] + bv.y);
                } else {
                    const int cl = c - KD;
                    const float2 bv = *(const float2*)(bias2 + cl);
                    *(float2*)(Cl + (size_t)r0 * Dd + cl) =
                        make_float2(acc[mi][ni][0] + bv.x, acc[mi][ni][1] + bv.y);
                    *(float2*)(Cl + (size_t)(r0 + 8) * Dd + cl) =
                        make_float2(acc[mi][ni][2] + bv.x, acc[mi][ni][3] + bv.y);
                }
            }
        }
    } else {
        #pragma unroll
        for (int mi = 0; mi < MT; mi++) {
            const int r0 = m0 + wm * MSLAB + mi * 16 + gid;
            #pragma unroll
            for (int ni = 0; ni < 4; ni++) {
                const int c = n0 + wn * 32 + ni * 8 + tig * 2;
                const float2 bv = *(const float2*)(bias + c);
                *(__half2*)(C + (size_t)r0 * N + c) =
                    __floats2half2_rn(acc[mi][ni][0] + bv.x, acc[mi][ni][1] + bv.y);
                *(__half2*)(C + (size_t)(r0 + 8) * N + c) =
                    __floats2half2_rn(acc[mi][ni][2] + bv.x, acc[mi][ni][3] + bv.y);
            }
        }
    }
}

// ===========================================================================
// Converters: one 3-segment contiguous kernel + one 2-segment strided kernel
// ===========================================================================
__global__ void cvt3_k(const float* __restrict__ s0, __half* __restrict__ d0, int n0,
                       const float* __restrict__ s1, __half* __restrict__ d1, int n1,
                       const float* __restrict__ s2, __half* __restrict__ d2, int n2)
{
    int i = (blockIdx.x * blockDim.x + threadIdx.x) * 4;
    const float* s; __half* d; int off;
    if (i < n0)                { s = s0; d = d0; off = i; }
    else if (i < n0 + n1)      { s = s1; d = d1; off = i - n0; }
    else if (i < n0 + n1 + n2) { s = s2; d = d2; off = i - n0 - n1; }
    else return;
    float4 v = *(const float4*)(s + off);
    __half2* p = (__half2*)(d + off);
    p[0] = __floats2half2_rn(v.x, v.y);
    p[1] = __floats2half2_rn(v.z, v.w);
}

// Wd [H2,KD] -> Wch cols [0,KD); Wa [H2,Dd] -> Wch cols [KD,NC)
__global__ void cvt_wch_k(const float* __restrict__ wd, const float* __restrict__ wa,
                          __half* __restrict__ wch)
{
    int i = (blockIdx.x * blockDim.x + threadIdx.x) * 4;
    const int nWd = H2 * KD;
    const float* s; int r, c;
    if (i < nWd)            { s = wd; r = i / KD; c = i % KD; }
    else if (i < nWd + H2 * Dd) { int k = i - nWd; s = wa; r = k / Dd; c = KD + (k % Dd); }
    else return;
    float4 v = *(const float4*)(s + (i < nWd ? i : i - nWd));
    __half2* p = (__half2*)(wch + (size_t)r * NC + c);
    p[0] = __floats2half2_rn(v.x, v.y);
    p[1] = __floats2half2_rn(v.z, v.w);
}

// ===========================================================================
// Block reduction (for LN)
// ===========================================================================
__device__ __forceinline__ float blockSumN(float v, float* red, int nw) {
    #pragma unroll
    for (int o = 16; o > 0; o >>= 1) v += __shfl_down_sync(0xffffffffu, v, o);
    const int lane = threadIdx.x & 31, w = threadIdx.x >> 5;
    if (lane == 0) red[w] = v;
    __syncthreads();
    if (w == 0) {
        v = (lane < nw) ? red[lane] : 0.f;
        #pragma unroll
        for (int o = 4; o > 0; o >>= 1) v += __shfl_down_sync(0xffffffffu, v, o);
        if (lane == 0) red[0] = v;
    }
    __syncthreads();
    float out = red[0];
    __syncthreads();
    return out;
}

// ===========================================================================
// One-pass LayerNorm + ReLU, in-place on fp16 (stats in fp32).
// ===========================================================================
__global__ void ln_relu_h(__half* __restrict__ x, const float* __restrict__ g,
                          const float* __restrict__ be)
{
    __shared__ float red[8];
    const int H = blockDim.x * 4;
    const int nw = blockDim.x >> 5;
    __half2* xp = (__half2*)(x + (size_t)blockIdx.x * H);
    __half2 a = xp[threadIdx.x * 2];
    __half2 b = xp[threadIdx.x * 2 + 1];
    float2 va = __half22float2(a);
    float2 vb = __half22float2(b);

    float s  = va.x + va.y + vb.x + vb.y;
    float s2 = va.x * va.x + va.y * va.y + vb.x * vb.x + vb.y * vb.y;
    s  = blockSumN(s, red, nw);
    s2 = blockSumN(s2, red, nw);
    const float mu  = s / H;
    const float var = s2 / H - mu * mu;
    const float rs  = rsqrtf(var + 1e-5f);

    float4 gg = ((const float4*)g)[threadIdx.x];
    float4 bbv = ((const float4*)be)[threadIdx.x];
    float o0 = fmaxf((va.x - mu) * rs * gg.x + bbv.x, 0.f);
    float o1 = fmaxf((va.y - mu) * rs * gg.y + bbv.y, 0.f);
    float o2 = fmaxf((vb.x - mu) * rs * gg.z + bbv.z, 0.f);
    float o3 = fmaxf((vb.y - mu) * rs * gg.w + bbv.w, 0.f);
    xp[threadIdx.x * 2]     = __floats2half2_rn(o0, o1);
    xp[threadIdx.x * 2 + 1] = __floats2half2_rn(o2, o3);
}

// ===========================================================================
// Warp-per-row epilogue: softmax(fp32 logits) -> attn; W = fp16 wflat * attn;
// Gram-Schmidt K=4. 256-thread blocks = 8 rows/block. No __syncthreads.
// ===========================================================================
__device__ __forceinline__ float warpSum(float v) {
    #pragma unroll
    for (int o = 16; o > 0; o >>= 1) v += __shfl_xor_sync(0xffffffffu, v, o);
    return v;
}
__device__ __forceinline__ float warpMax(float v) {
    #pragma unroll
    for (int o = 16; o > 0; o >>= 1) v = fmaxf(v, __shfl_xor_sync(0xffffffffu, v, o));
    return v;
}

__global__ void epilogue_warp(const __half* __restrict__ wflath,
                              const float* __restrict__ logits,
                              float* __restrict__ out)
{
    const int row  = blockIdx.x * 8 + (threadIdx.x >> 5);
    const int lane = threadIdx.x & 31;
    constexpr int J = Dd / 32;  // 24
    const float* lrow = logits + (size_t)row * Dd;
    const __half* wrow = wflath + (size_t)row * KD;

    float l[J];
    float m = -INFINITY;
    #pragma unroll
    for (int j = 0; j < J; j++) {
        l[j] = lrow[lane + j * 32];
        m = fmaxf(m, l[j]);
    }
    m = warpMax(m);
    float s = 0.f;
    #pragma unroll
    for (int j = 0; j < J; j++) { l[j] = expf(l[j] - m); s += l[j]; }
    s = warpSum(s);
    const float inv_s = 1.f / s;
    float* out_attn = out + (size_t)Bsz * KD;
    #pragma unroll
    for (int j = 0; j < J; j++) {
        l[j] *= inv_s;                       // l[] now holds attn
        out_attn[(size_t)row * Dd + lane + j * 32] = l[j];
    }

    float wv[Kk][J];
    #pragma unroll
    for (int k = 0; k < Kk; k++)
        #pragma unroll
        for (int j = 0; j < J; j++)
            wv[k][j] = __half2float(wrow[k * Dd + lane + j * 32]) * l[j];

    #pragma unroll
    for (int k = 0; k < Kk; k++) {
        #pragma unroll
        for (int p = 0; p < k; p++) {
            float d = 0.f;
            #pragma unroll
            for (int j = 0; j < J; j++) d += wv[k][j] * wv[p][j];
            d = warpSum(d);
            #pragma unroll
            for (int j = 0; j < J; j++) wv[k][j] -= d * wv[p][j];
        }
        float n2 = 0.f;
        #pragma unroll
        for (int j = 0; j < J; j++) n2 += wv[k][j] * wv[k][j];
        n2 = warpSum(n2);
        const float inv = 1.f / fmaxf(sqrtf(n2), 1e-12f);
        #pragma unroll
        for (int j = 0; j < J; j++) {
            wv[k][j] *= inv;
            out[(size_t)row * KD + k * Dd + lane + j * 32] = wv[k][j];
        }
    }
}

// ===========================================================================
extern "C" void kernel_launch(void* const* d_in, const int* in_sizes, int n_in,
                              void* d_out, int out_size)
{
    const float* emb = (const float*)d_in[0];
    const float* W1  = (const float*)d_in[1];
    const float* b1  = (const float*)d_in[2];
    const float* g1  = (const float*)d_in[3];
    const float* be1 = (const float*)d_in[4];
    const float* W2  = (const float*)d_in[5];
    const float* b2  = (const float*)d_in[6];
    const float* g2  = (const float*)d_in[7];
    const float* be2 = (const float*)d_in[8];
    const float* Wd  = (const float*)d_in[9];
    const float* bd  = (const float*)d_in[10];
    const float* Wa  = (const float*)d_in[11];
    const float* ba  = (const float*)d_in[12];
    float* out = (float*)d_out;

    float *logits;
    __half *wflath, *embh, *h1h, *h2h, *W1h, *W2h, *Wch;
    cudaGetSymbolAddress((void**)&logits, g_logits);
    cudaGetSymbolAddress((void**)&wflath, g_wflath);
    cudaGetSymbolAddress((void**)&embh, g_embh);
    cudaGetSymbolAddress((void**)&h1h, g_h1h);
    cudaGetSymbolAddress((void**)&h2h, g_h2h);
    cudaGetSymbolAddress((void**)&W1h, g_W1h);
    cudaGetSymbolAddress((void**)&W2h, g_W2h);
    cudaGetSymbolAddress((void**)&Wch, g_Wch);

    cudaFuncSetAttribute((const void*)mma_gemm<128, false>,
                         cudaFuncAttributeMaxDynamicSharedMemorySize, GemmCfg<128>::SMEM);
    cudaFuncSetAttribute((const void*)mma_gemm<64, false>,
                         cudaFuncAttributeMaxDynamicSharedMemorySize, GemmCfg<64>::SMEM);
    cudaFuncSetAttribute((const void*)mma_gemm<128, true>,
                         cudaFuncAttributeMaxDynamicSharedMemorySize, GemmCfg<128>::SMEM);

    // Converts: emb + W1 + W2 in one kernel; Wd + Wa -> Wch in one kernel
    {
        int n0 = Bsz * Dd, n1 = Dd * H1, n2 = H1 * H2;
        int q = (n0 + n1 + n2) / 4;
        cvt3_k<<<(q + 255) / 256, 256>>>(emb, embh, n0, W1, W1h, n1, W2, W2h, n2);
    }
    {
        int q = (H2 * KD + H2 * Dd) / 4;
        cvt_wch_k<<<(q + 255) / 256, 256>>>(Wd, Wa, Wch);
    }

    // Layer 1 (BM=128, R13-best): fp16 out, LN in-place on fp16
    mma_gemm<128, false><<<dim3(H1 / BN, Bsz / 128), 256, GemmCfg<128>::SMEM>>>(
        embh, W1h, b1, h1h, nullptr, nullptr, nullptr, Bsz, H1, Dd);
    ln_relu_h<<<Bsz, H1 / 4>>>(h1h, g1, be1);
    // Layer 2 (BM=64: grid 512 CTAs -> full wave at 3 CTAs/SM)
    mma_gemm<64, false><<<dim3(H2 / BN, Bsz / 64), 256, GemmCfg<64>::SMEM>>>(
        h1h, W2h, b2, h2h, nullptr, nullptr, nullptr, Bsz, H2, H1);
    ln_relu_h<<<Bsz, H2 / 4>>>(h2h, g2, be2);
    // Merged heads with mixed store (BM=128): wflat -> fp16, logits -> fp32
    mma_gemm<128, true><<<dim3(NC / BN, Bsz / 128), 256, GemmCfg<128>::SMEM>>>(
        h2h, Wch, bd, nullptr, ba, wflath, logits, Bsz, NC, H2);
    // softmax + modulate + Gram-Schmidt (warp per row, 8 rows/block)
    epilogue_warp<<<Bsz / 8, 256>>>(wflath, logits, out);
}

// round 16
// speedup vs baseline: 1.0755x; 1.0189x over previous
#include <cuda_runtime.h>
#include <cuda_fp16.h>
#include <math.h>
#include <cstdint>

// Problem dims (compile-time)
static constexpr int Bsz = 16384;
static constexpr int Dd  = 768;
static constexpr int Kk  = 4;
static constexpr int H1  = 512;
static constexpr int H2  = 256;
static constexpr int KD  = Kk * Dd;        // 3072
static constexpr int NC  = KD + Dd;        // 3840 combined head width

// Scratch (device globals: allocation-free per harness rules)
__device__ float  g_logits[Bsz * Dd];      // fp32 (softmax input precision)
__device__ __half g_wflath[Bsz * KD];      // fp16 wflat scratch
__device__ __half g_embh[Bsz * Dd];
__device__ __half g_h1h[Bsz * H1];
__device__ __half g_h2h[Bsz * H2];
__device__ __half g_W1h[Dd * H1];
__device__ __half g_W2h[H1 * H2];
__device__ __half g_Wch[H2 * NC];          // [Wd | Wa] fp16, row stride NC

__device__ __forceinline__ uint32_t smem_u32(const void* p) {
    uint32_t a;
    asm("{ .reg .u64 t; cvta.to.shared.u64 t, %1; cvt.u32.u64 %0, t; }"
        : "=r"(a) : "l"(p));
    return a;
}

__device__ __forceinline__ void cp_async16(uint32_t dst, const void* src) {
    asm volatile("cp.async.cg.shared.global [%0], [%1], 16;"
                 :: "r"(dst), "l"(src) : "memory");
}
#define CP_COMMIT() asm volatile("cp.async.commit_group;" ::: "memory")
#define CP_WAIT(n)  asm volatile("cp.async.wait_group %0;" :: "n"(n) : "memory")

// ===========================================================================
// FP16 mma GEMM (R13-best): fp16 gmem -> cp.async (3-stage) -> fp16 smem
// -> ldmatrix -> m16n8k16 (fp32 accum). BM=128, BN=128, BK=32, 256 threads,
// warp tile 64x32, 2 CTAs/SM.
// HEADS=true: block cols < KD -> fp16 wflath (stride KD); cols >= KD ->
//             fp32 logits (stride Dd); bias from bias/bias2.
// ===========================================================================
#define BM 128
#define BN 128
#define BKt 32

static constexpr int AS_STRIDE = 40;    // halves, conflict-free ldmatrix phases
static constexpr int BS_STRIDE = 136;
static constexpr int AS_ELEMS  = BM * AS_STRIDE;   // 5120 halves
static constexpr int BS_ELEMS  = BKt * BS_STRIDE;  // 4352 halves
static constexpr int NSTAGE    = 3;
static constexpr int GEMM_SMEM_BYTES = NSTAGE * (AS_ELEMS + BS_ELEMS) * 2; // 56832

template <bool HEADS>
__global__ __launch_bounds__(256, 2) void mma_gemm(
    const __half* __restrict__ A, const __half* __restrict__ B,
    const float* __restrict__ bias, __half* __restrict__ C,
    const float* __restrict__ bias2,          // HEADS: ba
    __half* __restrict__ Cw,                  // HEADS: wflath
    float* __restrict__ Cl,                   // HEADS: logits
    int M, int N, int Kdim)
{
    extern __shared__ __half hsm[];
    const uint32_t aBase = smem_u32(hsm);
    const uint32_t bBase = aBase + NSTAGE * AS_ELEMS * 2;

    const int tid  = threadIdx.x;
    const int lane = tid & 31;
    const int w    = tid >> 5;
    const int wm   = w >> 2;          // 0..1
    const int wn   = w & 3;           // 0..3
    const int gid  = lane >> 2;       // 0..7
    const int tig  = lane & 3;        // 0..3

    const int m0 = blockIdx.y * BM;
    const int n0 = blockIdx.x * BN;

    float acc[4][4][4];
    #pragma unroll
    for (int i = 0; i < 4; i++)
        #pragma unroll
        for (int j = 0; j < 4; j++)
            #pragma unroll
            for (int r = 0; r < 4; r++) acc[i][j][r] = 0.f;

    const int nch = Kdim / BKt;

    auto stage = [&](int kc, int s) {
        const uint32_t aB = aBase + s * AS_ELEMS * 2;
        const uint32_t bB = bBase + s * BS_ELEMS * 2;
        const int k0 = kc * BKt;
        #pragma unroll
        for (int it = 0; it < 2; it++) {
            int sid = tid + it * 256;
            int ar = sid >> 2, as = sid & 3;
            cp_async16(aB + (ar * AS_STRIDE + as * 8) * 2,
                       A + (size_t)(m0 + ar) * Kdim + k0 + as * 8);
            int br = sid >> 4, bs = sid & 15;
            cp_async16(bB + (br * BS_STRIDE + bs * 8) * 2,
                       B + (size_t)(k0 + br) * N + n0 + bs * 8);
        }
    };

    stage(0, 0); CP_COMMIT();
    stage(1, 1); CP_COMMIT();

    for (int kc = 0; kc < nch; kc++) {
        const int cur = kc % NSTAGE;
        if (kc < nch - 1) { CP_WAIT(1); } else { CP_WAIT(0); }
        __syncthreads();
        if (kc + 2 < nch) { stage(kc + 2, (kc + 2) % NSTAGE); CP_COMMIT(); }

        const uint32_t aCur = aBase + cur * AS_ELEMS * 2;
        const uint32_t bCur = bBase + cur * BS_ELEMS * 2;

        #pragma unroll
        for (int ks = 0; ks < 2; ks++) {
            const int kb = ks * 16;
            uint32_t af[4][4];
            #pragma unroll
            for (int mi = 0; mi < 4; mi++) {
                const int r = wm * 64 + mi * 16;
                uint32_t addr = aCur
                    + (uint32_t)(r + (lane & 15)) * (AS_STRIDE * 2)
                    + kb * 2 + (lane >> 4) * 16;
                asm volatile(
                    "ldmatrix.sync.aligned.m8n8.x4.shared.b16 {%0,%1,%2,%3}, [%4];"
                    : "=r"(af[mi][0]), "=r"(af[mi][1]),
                      "=r"(af[mi][2]), "=r"(af[mi][3]) : "r"(addr));
            }
            uint32_t bf[4][2];
            #pragma unroll
            for (int nj = 0; nj < 2; nj++) {
                const int c = wn * 32 + nj * 16;
                uint32_t addr = bCur
                    + (uint32_t)(kb + ((lane >> 3) & 1) * 8 + (lane & 7)) * (BS_STRIDE * 2)
                    + (uint32_t)(c + (lane >> 4) * 8) * 2;
                asm volatile(
                    "ldmatrix.sync.aligned.m8n8.x4.trans.shared.b16 {%0,%1,%2,%3}, [%4];"
                    : "=r"(bf[nj * 2][0]), "=r"(bf[nj * 2][1]),
                      "=r"(bf[nj * 2 + 1][0]), "=r"(bf[nj * 2 + 1][1]) : "r"(addr));
            }
            #pragma unroll
            for (int mi = 0; mi < 4; mi++)
                #pragma unroll
                for (int ni = 0; ni < 4; ni++) {
                    asm volatile(
                        "mma.sync.aligned.m16n8k16.row.col.f32.f16.f16.f32 "
                        "{%0,%1,%2,%3}, {%4,%5,%6,%7}, {%8,%9}, {%0,%1,%2,%3};"
                        : "+f"(acc[mi][ni][0]), "+f"(acc[mi][ni][1]),
                          "+f"(acc[mi][ni][2]), "+f"(acc[mi][ni][3])
                        : "r"(af[mi][0]), "r"(af[mi][1]), "r"(af[mi][2]), "r"(af[mi][3]),
                          "r"(bf[ni][0]), "r"(bf[ni][1]));
                }
        }
    }

    // Epilogue
    if constexpr (HEADS) {
        const bool isW = (n0 < KD);   // whole block is one region (KD % BN == 0)
        #pragma unroll
        for (int mi = 0; mi < 4; mi++) {
            const int r0 = m0 + wm * 64 + mi * 16 + gid;
            #pragma unroll
            for (int ni = 0; ni < 4; ni++) {
                const int c = n0 + wn * 32 + ni * 8 + tig * 2;
                if (isW) {
                    const float2 bv = *(const float2*)(bias + c);
                    *(__half2*)(Cw + (size_t)r0 * KD + c) =
                        __floats2half2_rn(acc[mi][ni][0] + bv.x, acc[mi][ni][1] + bv.y);
                    *(__half2*)(Cw + (size_t)(r0 + 8) * KD + c) =
                        __floats2half2_rn(acc[mi][ni][2] + bv.x, acc[mi][ni][3] + bv.y);
                } else {
                    const int cl = c - KD;
                    const float2 bv = *(const float2*)(bias2 + cl);
                    *(float2*)(Cl + (size_t)r0 * Dd + cl) =
                        make_float2(acc[mi][ni][0] + bv.x, acc[mi][ni][1] + bv.y);
                    *(float2*)(Cl + (size_t)(r0 + 8) * Dd + cl) =
                        make_float2(acc[mi][ni][2] + bv.x, acc[mi][ni][3] + bv.y);
                }
            }
        }
    } else {
        #pragma unroll
        for (int mi = 0; mi < 4; mi++) {
            const int r0 = m0 + wm * 64 + mi * 16 + gid;
            #pragma unroll
            for (int ni = 0; ni < 4; ni++) {
                const int c = n0 + wn * 32 + ni * 8 + tig * 2;
                const float2 bv = *(const float2*)(bias + c);
                *(__half2*)(C + (size_t)r0 * N + c) =
                    __floats2half2_rn(acc[mi][ni][0] + bv.x, acc[mi][ni][1] + bv.y);
                *(__half2*)(C + (size_t)(r0 + 8) * N + c) =
                    __floats2half2_rn(acc[mi][ni][2] + bv.x, acc[mi][ni][3] + bv.y);
            }
        }
    }
}

// ===========================================================================
// Converters: one 3-segment contiguous kernel + one 2-segment strided kernel
// ===========================================================================
__global__ void cvt3_k(const float* __restrict__ s0, __half* __restrict__ d0, int n0,
                       const float* __restrict__ s1, __half* __restrict__ d1, int n1,
                       const float* __restrict__ s2, __half* __restrict__ d2, int n2)
{
    int i = (blockIdx.x * blockDim.x + threadIdx.x) * 4;
    const float* s; __half* d; int off;
    if (i < n0)                { s = s0; d = d0; off = i; }
    else if (i < n0 + n1)      { s = s1; d = d1; off = i - n0; }
    else if (i < n0 + n1 + n2) { s = s2; d = d2; off = i - n0 - n1; }
    else return;
    float4 v = *(const float4*)(s + off);
    __half2* p = (__half2*)(d + off);
    p[0] = __floats2half2_rn(v.x, v.y);
    p[1] = __floats2half2_rn(v.z, v.w);
}

// Wd [H2,KD] -> Wch cols [0,KD); Wa [H2,Dd] -> Wch cols [KD,NC)
__global__ void cvt_wch_k(const float* __restrict__ wd, const float* __restrict__ wa,
                          __half* __restrict__ wch)
{
    int i = (blockIdx.x * blockDim.x + threadIdx.x) * 4;
    const int nWd = H2 * KD;
    const float* s; int r, c, off;
    if (i < nWd)                { s = wd; off = i; r = off / KD; c = off % KD; }
    else if (i < nWd + H2 * Dd) { s = wa; off = i - nWd; r = off / Dd; c = KD + (off % Dd); }
    else return;
    float4 v = *(const float4*)(s + off);
    __half2* p = (__half2*)(wch + (size_t)r * NC + c);
    p[0] = __floats2half2_rn(v.x, v.y);
    p[1] = __floats2half2_rn(v.z, v.w);
}

// ===========================================================================
// One-pass LayerNorm + ReLU, in-place on fp16 (stats in fp32).
// 8 halves (uint4) per thread: H1 row = 64 threads (2 warps),
// H2 row = 32 threads (1 warp). Warp butterfly + 2-entry smem exchange.
// ===========================================================================
__device__ __forceinline__ float warpSumB(float v) {
    #pragma unroll
    for (int o = 16; o > 0; o >>= 1) v += __shfl_xor_sync(0xffffffffu, v, o);
    return v;
}

template <int H>
__global__ void ln_relu_h8(__half* __restrict__ x, const float* __restrict__ g,
                           const float* __restrict__ be)
{
    constexpr int NT = H / 8;          // threads per row (64 or 32)
    constexpr int NW = NT / 32;        // warps (2 or 1)
    __shared__ float red[2][2];        // [stat][warp]
    const int tid = threadIdx.x;

    uint4* xp = (uint4*)(x + (size_t)blockIdx.x * H);
    uint4 u = xp[tid];
    __half2 h0 = *(__half2*)&u.x, h1 = *(__half2*)&u.y;
    __half2 h2 = *(__half2*)&u.z, h3 = *(__half2*)&u.w;
    float2 v0 = __half22float2(h0), v1 = __half22float2(h1);
    float2 v2 = __half22float2(h2), v3 = __half22float2(h3);

    float s  = v0.x + v0.y + v1.x + v1.y + v2.x + v2.y + v3.x + v3.y;
    float s2 = v0.x * v0.x + v0.y * v0.y + v1.x * v1.x + v1.y * v1.y
             + v2.x * v2.x + v2.y * v2.y + v3.x * v3.x + v3.y * v3.y;
    s  = warpSumB(s);
    s2 = warpSumB(s2);
    if constexpr (NW == 2) {
        const int wid = tid >> 5;
        if ((tid & 31) == 0) { red[0][wid] = s; red[1][wid] = s2; }
        __syncthreads();
        s  = red[0][0] + red[0][1];
        s2 = red[1][0] + red[1][1];
    }
    const float mu  = s / H;
    const float var = s2 / H - mu * mu;
    const float rs  = rsqrtf(var + 1e-5f);

    const float4 g0 = ((const float4*)g)[tid * 2];
    const float4 g1 = ((const float4*)g)[tid * 2 + 1];
    const float4 b0 = ((const float4*)be)[tid * 2];
    const float4 b1 = ((const float4*)be)[tid * 2 + 1];

    __half2 o0 = __floats2half2_rn(fmaxf((v0.x - mu) * rs * g0.x + b0.x, 0.f),
                                   fmaxf((v0.y - mu) * rs * g0.y + b0.y, 0.f));
    __half2 o1 = __floats2half2_rn(fmaxf((v1.x - mu) * rs * g0.z + b0.z, 0.f),
                                   fmaxf((v1.y - mu) * rs * g0.w + b0.w, 0.f));
    __half2 o2 = __floats2half2_rn(fmaxf((v2.x - mu) * rs * g1.x + b1.x, 0.f),
                                   fmaxf((v2.y - mu) * rs * g1.y + b1.y, 0.f));
    __half2 o3 = __floats2half2_rn(fmaxf((v3.x - mu) * rs * g1.z + b1.z, 0.f),
                                   fmaxf((v3.y - mu) * rs * g1.w + b1.w, 0.f));
    uint4 o;
    *(__half2*)&o.x = o0; *(__half2*)&o.y = o1;
    *(__half2*)&o.z = o2; *(__half2*)&o.w = o3;
    xp[tid] = o;
}

// ===========================================================================
// Warp-per-row epilogue (R13 config: 128 threads = 4 rows/block, 3 CTAs/SM):
// softmax(fp32 logits) -> attn; W = fp16 wflat * attn; Gram-Schmidt K=4.
// ===========================================================================
__device__ __forceinline__ float warpSum(float v) {
    #pragma unroll
    for (int o = 16; o > 0; o >>= 1) v += __shfl_xor_sync(0xffffffffu, v, o);
    return v;
}
__device__ __forceinline__ float warpMax(float v) {
    #pragma unroll
    for (int o = 16; o > 0; o >>= 1) v = fmaxf(v, __shfl_xor_sync(0xffffffffu, v, o));
    return v;
}

__global__ void epilogue_warp(const __half* __restrict__ wflath,
                              const float* __restrict__ logits,
                              float* __restrict__ out)
{
    const int row  = blockIdx.x * 4 + (threadIdx.x >> 5);
    const int lane = threadIdx.x & 31;
    constexpr int J = Dd / 32;  // 24
    const float* lrow = logits + (size_t)row * Dd;
    const __half* wrow = wflath + (size_t)row * KD;

    float l[J];
    float m = -INFINITY;
    #pragma unroll
    for (int j = 0; j < J; j++) {
        l[j] = lrow[lane + j * 32];
        m = fmaxf(m, l[j]);
    }
    m = warpMax(m);
    float s = 0.f;
    #pragma unroll
    for (int j = 0; j < J; j++) { l[j] = expf(l[j] - m); s += l[j]; }
    s = warpSum(s);
    const float inv_s = 1.f / s;
    float* out_attn = out + (size_t)Bsz * KD;
    #pragma unroll
    for (int j = 0; j < J; j++) {
        l[j] *= inv_s;                       // l[] now holds attn
        out_attn[(size_t)row * Dd + lane + j * 32] = l[j];
    }

    float wv[Kk][J];
    #pragma unroll
    for (int k = 0; k < Kk; k++)
        #pragma unroll
        for (int j = 0; j < J; j++)
            wv[k][j] = __half2float(wrow[k * Dd + lane + j * 32]) * l[j];

    #pragma unroll
    for (int k = 0; k < Kk; k++) {
        #pragma unroll
        for (int p = 0; p < k; p++) {
            float d = 0.f;
            #pragma unroll
            for (int j = 0; j < J; j++) d += wv[k][j] * wv[p][j];
            d = warpSum(d);
            #pragma unroll
            for (int j = 0; j < J; j++) wv[k][j] -= d * wv[p][j];
        }
        float n2 = 0.f;
        #pragma unroll
        for (int j = 0; j < J; j++) n2 += wv[k][j] * wv[k][j];
        n2 = warpSum(n2);
        const float inv = 1.f / fmaxf(sqrtf(n2), 1e-12f);
        #pragma unroll
        for (int j = 0; j < J; j++) {
            wv[k][j] *= inv;
            out[(size_t)row * KD + k * Dd + lane + j * 32] = wv[k][j];
        }
    }
}

// ===========================================================================
extern "C" void kernel_launch(void* const* d_in, const int* in_sizes, int n_in,
                              void* d_out, int out_size)
{
    const float* emb = (const float*)d_in[0];
    const float* W1  = (const float*)d_in[1];
    const float* b1  = (const float*)d_in[2];
    const float* g1  = (const float*)d_in[3];
    const float* be1 = (const float*)d_in[4];
    const float* W2  = (const float*)d_in[5];
    const float* b2  = (const float*)d_in[6];
    const float* g2  = (const float*)d_in[7];
    const float* be2 = (const float*)d_in[8];
    const float* Wd  = (const float*)d_in[9];
    const float* bd  = (const float*)d_in[10];
    const float* Wa  = (const float*)d_in[11];
    const float* ba  = (const float*)d_in[12];
    float* out = (float*)d_out;

    float *logits;
    __half *wflath, *embh, *h1h, *h2h, *W1h, *W2h, *Wch;
    cudaGetSymbolAddress((void**)&logits, g_logits);
    cudaGetSymbolAddress((void**)&wflath, g_wflath);
    cudaGetSymbolAddress((void**)&embh, g_embh);
    cudaGetSymbolAddress((void**)&h1h, g_h1h);
    cudaGetSymbolAddress((void**)&h2h, g_h2h);
    cudaGetSymbolAddress((void**)&W1h, g_W1h);
    cudaGetSymbolAddress((void**)&W2h, g_W2h);
    cudaGetSymbolAddress((void**)&Wch, g_Wch);

    cudaFuncSetAttribute((const void*)mma_gemm<false>,
                         cudaFuncAttributeMaxDynamicSharedMemorySize, GEMM_SMEM_BYTES);
    cudaFuncSetAttribute((const void*)mma_gemm<true>,
                         cudaFuncAttributeMaxDynamicSharedMemorySize, GEMM_SMEM_BYTES);

    // Converts: emb + W1 + W2 in one kernel; Wd + Wa -> Wch in one kernel
    {
        int n0 = Bsz * Dd, n1 = Dd * H1, n2 = H1 * H2;
        int q = (n0 + n1 + n2) / 4;
        cvt3_k<<<(q + 255) / 256, 256>>>(emb, embh, n0, W1, W1h, n1, W2, W2h, n2);
    }
    {
        int q = (H2 * KD + H2 * Dd) / 4;
        cvt_wch_k<<<(q + 255) / 256, 256>>>(Wd, Wa, Wch);
    }

    // Layer 1 (R13 config): fp16 out, LN in-place on fp16 (8 halves/thread)
    mma_gemm<false><<<dim3(H1 / BN, Bsz / BM), 256, GEMM_SMEM_BYTES>>>(
        embh, W1h, b1, h1h, nullptr, nullptr, nullptr, Bsz, H1, Dd);
    ln_relu_h8<H1><<<Bsz, H1 / 8>>>(h1h, g1, be1);
    // Layer 2
    mma_gemm<false><<<dim3(H2 / BN, Bsz / BM), 256, GEMM_SMEM_BYTES>>>(
        h1h, W2h, b2, h2h, nullptr, nullptr, nullptr, Bsz, H2, H1);
    ln_relu_h8<H2><<<Bsz, H2 / 8>>>(h2h, g2, be2);
    // Merged heads with mixed store: wflat -> fp16, logits -> fp32
    mma_gemm<true><<<dim3(NC / BN, Bsz / BM), 256, GEMM_SMEM_BYTES>>>(
        h2h, Wch, bd, nullptr, ba, wflath, logits, Bsz, NC, H2);
    // softmax + modulate + Gram-Schmidt (warp per row, 4 rows/block)
    epilogue_warp<<<Bsz / 4, 128>>>(wflath, logits, out);
}

// round 17
// speedup vs baseline: 1.1024x; 1.0251x over previous
#include <cuda_runtime.h>
#include <cuda_fp16.h>
#include <math.h>
#include <cstdint>

// Problem dims (compile-time)
static constexpr int Bsz = 16384;
static constexpr int Dd  = 768;
static constexpr int Kk  = 4;
static constexpr int H1  = 512;
static constexpr int H2  = 256;
static constexpr int KD  = Kk * Dd;        // 3072
static constexpr int NC  = KD + Dd;        // 3840 combined head width

// Scratch (device globals: allocation-free per harness rules)
__device__ float  g_logits[Bsz * Dd];      // fp32 (softmax input precision)
__device__ __half g_wflath[Bsz * KD];      // fp16 wflat scratch
__device__ __half g_embh[Bsz * Dd];
__device__ __half g_h1h[Bsz * H1];
__device__ __half g_h2h[Bsz * H2];
__device__ __half g_W1h[Dd * H1];
__device__ __half g_W2h[H1 * H2];
__device__ __half g_Wch[H2 * NC];          // [Wd | Wa] fp16, row stride NC

__device__ __forceinline__ uint32_t smem_u32(const void* p) {
    uint32_t a;
    asm("{ .reg .u64 t; cvta.to.shared.u64 t, %1; cvt.u32.u64 %0, t; }"
        : "=r"(a) : "l"(p));
    return a;
}

__device__ __forceinline__ void cp_async16(uint32_t dst, const void* src) {
    asm volatile("cp.async.cg.shared.global [%0], [%1], 16;"
                 :: "r"(dst), "l"(src) : "memory");
}
#define CP_COMMIT() asm volatile("cp.async.commit_group;" ::: "memory")
#define CP_WAIT(n)  asm volatile("cp.async.wait_group %0;" :: "n"(n) : "memory")

// ===========================================================================
// FP16 mma GEMM (R13-best): fp16 gmem -> cp.async (3-stage) -> fp16 smem
// -> ldmatrix -> m16n8k16 (fp32 accum). BM=128, BN=128, BK=32, 256 threads,
// warp tile 64x32, 2 CTAs/SM.
// HEADS=true: block cols < KD -> fp16 wflath (stride KD); cols >= KD ->
//             fp32 logits (stride Dd); bias from bias/bias2.
// ===========================================================================
#define BM 128
#define BN 128
#define BKt 32

static constexpr int AS_STRIDE = 40;    // halves, conflict-free ldmatrix phases
static constexpr int BS_STRIDE = 136;
static constexpr int AS_ELEMS  = BM * AS_STRIDE;   // 5120 halves
static constexpr int BS_ELEMS  = BKt * BS_STRIDE;  // 4352 halves
static constexpr int NSTAGE    = 3;
static constexpr int GEMM_SMEM_BYTES = NSTAGE * (AS_ELEMS + BS_ELEMS) * 2; // 56832

template <bool HEADS>
__global__ __launch_bounds__(256, 2) void mma_gemm(
    const __half* __restrict__ A, const __half* __restrict__ B,
    const float* __restrict__ bias, __half* __restrict__ C,
    const float* __restrict__ bias2,          // HEADS: ba
    __half* __restrict__ Cw,                  // HEADS: wflath
    float* __restrict__ Cl,                   // HEADS: logits
    int M, int N, int Kdim)
{
    extern __shared__ __half hsm[];
    const uint32_t aBase = smem_u32(hsm);
    const uint32_t bBase = aBase + NSTAGE * AS_ELEMS * 2;

    const int tid  = threadIdx.x;
    const int lane = tid & 31;
    const int w    = tid >> 5;
    const int wm   = w >> 2;          // 0..1
    const int wn   = w & 3;           // 0..3
    const int gid  = lane >> 2;       // 0..7
    const int tig  = lane & 3;        // 0..3

    const int m0 = blockIdx.y * BM;
    const int n0 = blockIdx.x * BN;

    float acc[4][4][4];
    #pragma unroll
    for (int i = 0; i < 4; i++)
        #pragma unroll
        for (int j = 0; j < 4; j++)
            #pragma unroll
            for (int r = 0; r < 4; r++) acc[i][j][r] = 0.f;

    const int nch = Kdim / BKt;

    auto stage = [&](int kc, int s) {
        const uint32_t aB = aBase + s * AS_ELEMS * 2;
        const uint32_t bB = bBase + s * BS_ELEMS * 2;
        const int k0 = kc * BKt;
        #pragma unroll
        for (int it = 0; it < 2; it++) {
            int sid = tid + it * 256;
            int ar = sid >> 2, as = sid & 3;
            cp_async16(aB + (ar * AS_STRIDE + as * 8) * 2,
                       A + (size_t)(m0 + ar) * Kdim + k0 + as * 8);
            int br = sid >> 4, bs = sid & 15;
            cp_async16(bB + (br * BS_STRIDE + bs * 8) * 2,
                       B + (size_t)(k0 + br) * N + n0 + bs * 8);
        }
    };

    stage(0, 0); CP_COMMIT();
    stage(1, 1); CP_COMMIT();

    for (int kc = 0; kc < nch; kc++) {
        const int cur = kc % NSTAGE;
        if (kc < nch - 1) { CP_WAIT(1); } else { CP_WAIT(0); }
        __syncthreads();
        if (kc + 2 < nch) { stage(kc + 2, (kc + 2) % NSTAGE); CP_COMMIT(); }

        const uint32_t aCur = aBase + cur * AS_ELEMS * 2;
        const uint32_t bCur = bBase + cur * BS_ELEMS * 2;

        #pragma unroll
        for (int ks = 0; ks < 2; ks++) {
            const int kb = ks * 16;
            uint32_t af[4][4];
            #pragma unroll
            for (int mi = 0; mi < 4; mi++) {
                const int r = wm * 64 + mi * 16;
                uint32_t addr = aCur
                    + (uint32_t)(r + (lane & 15)) * (AS_STRIDE * 2)
                    + kb * 2 + (lane >> 4) * 16;
                asm volatile(
                    "ldmatrix.sync.aligned.m8n8.x4.shared.b16 {%0,%1,%2,%3}, [%4];"
                    : "=r"(af[mi][0]), "=r"(af[mi][1]),
                      "=r"(af[mi][2]), "=r"(af[mi][3]) : "r"(addr));
            }
            uint32_t bf[4][2];
            #pragma unroll
            for (int nj = 0; nj < 2; nj++) {
                const int c = wn * 32 + nj * 16;
                uint32_t addr = bCur
                    + (uint32_t)(kb + ((lane >> 3) & 1) * 8 + (lane & 7)) * (BS_STRIDE * 2)
                    + (uint32_t)(c + (lane >> 4) * 8) * 2;
                asm volatile(
                    "ldmatrix.sync.aligned.m8n8.x4.trans.shared.b16 {%0,%1,%2,%3}, [%4];"
                    : "=r"(bf[nj * 2][0]), "=r"(bf[nj * 2][1]),
                      "=r"(bf[nj * 2 + 1][0]), "=r"(bf[nj * 2 + 1][1]) : "r"(addr));
            }
            #pragma unroll
            for (int mi = 0; mi < 4; mi++)
                #pragma unroll
                for (int ni = 0; ni < 4; ni++) {
                    asm volatile(
                        "mma.sync.aligned.m16n8k16.row.col.f32.f16.f16.f32 "
                        "{%0,%1,%2,%3}, {%4,%5,%6,%7}, {%8,%9}, {%0,%1,%2,%3};"
                        : "+f"(acc[mi][ni][0]), "+f"(acc[mi][ni][1]),
                          "+f"(acc[mi][ni][2]), "+f"(acc[mi][ni][3])
                        : "r"(af[mi][0]), "r"(af[mi][1]), "r"(af[mi][2]), "r"(af[mi][3]),
                          "r"(bf[ni][0]), "r"(bf[ni][1]));
                }
        }
    }

    // Epilogue
    if constexpr (HEADS) {
        const bool isW = (n0 < KD);   // whole block is one region (KD % BN == 0)
        #pragma unroll
        for (int mi = 0; mi < 4; mi++) {
            const int r0 = m0 + wm * 64 + mi * 16 + gid;
            #pragma unroll
            for (int ni = 0; ni < 4; ni++) {
                const int c = n0 + wn * 32 + ni * 8 + tig * 2;
                if (isW) {
                    const float2 bv = *(const float2*)(bias + c);
                    *(__half2*)(Cw + (size_t)r0 * KD + c) =
                        __floats2half2_rn(acc[mi][ni][0] + bv.x, acc[mi][ni][1] + bv.y);
                    *(__half2*)(Cw + (size_t)(r0 + 8) * KD + c) =
                        __floats2half2_rn(acc[mi][ni][2] + bv.x, acc[mi][ni][3] + bv.y);
                } else {
                    const int cl = c - KD;
                    const float2 bv = *(const float2*)(bias2 + cl);
                    *(float2*)(Cl + (size_t)r0 * Dd + cl) =
                        make_float2(acc[mi][ni][0] + bv.x, acc[mi][ni][1] + bv.y);
                    *(float2*)(Cl + (size_t)(r0 + 8) * Dd + cl) =
                        make_float2(acc[mi][ni][2] + bv.x, acc[mi][ni][3] + bv.y);
                }
            }
        }
    } else {
        #pragma unroll
        for (int mi = 0; mi < 4; mi++) {
            const int r0 = m0 + wm * 64 + mi * 16 + gid;
            #pragma unroll
            for (int ni = 0; ni < 4; ni++) {
                const int c = n0 + wn * 32 + ni * 8 + tig * 2;
                const float2 bv = *(const float2*)(bias + c);
                *(__half2*)(C + (size_t)r0 * N + c) =
                    __floats2half2_rn(acc[mi][ni][0] + bv.x, acc[mi][ni][1] + bv.y);
                *(__half2*)(C + (size_t)(r0 + 8) * N + c) =
                    __floats2half2_rn(acc[mi][ni][2] + bv.x, acc[mi][ni][3] + bv.y);
            }
        }
    }
}

// ===========================================================================
// Converters: one 3-segment contiguous kernel + one 2-segment strided kernel
// ===========================================================================
__global__ void cvt3_k(const float* __restrict__ s0, __half* __restrict__ d0, int n0,
                       const float* __restrict__ s1, __half* __restrict__ d1, int n1,
                       const float* __restrict__ s2, __half* __restrict__ d2, int n2)
{
    int i = (blockIdx.x * blockDim.x + threadIdx.x) * 4;
    const float* s; __half* d; int off;
    if (i < n0)                { s = s0; d = d0; off = i; }
    else if (i < n0 + n1)      { s = s1; d = d1; off = i - n0; }
    else if (i < n0 + n1 + n2) { s = s2; d = d2; off = i - n0 - n1; }
    else return;
    float4 v = *(const float4*)(s + off);
    __half2* p = (__half2*)(d + off);
    p[0] = __floats2half2_rn(v.x, v.y);
    p[1] = __floats2half2_rn(v.z, v.w);
}

// Wd [H2,KD] -> Wch cols [0,KD); Wa [H2,Dd] -> Wch cols [KD,NC)
__global__ void cvt_wch_k(const float* __restrict__ wd, const float* __restrict__ wa,
                          __half* __restrict__ wch)
{
    int i = (blockIdx.x * blockDim.x + threadIdx.x) * 4;
    const int nWd = H2 * KD;
    const float* s; int r, c, off;
    if (i < nWd)                { s = wd; off = i; r = off / KD; c = off % KD; }
    else if (i < nWd + H2 * Dd) { s = wa; off = i - nWd; r = off / Dd; c = KD + (off % Dd); }
    else return;
    float4 v = *(const float4*)(s + off);
    __half2* p = (__half2*)(wch + (size_t)r * NC + c);
    p[0] = __floats2half2_rn(v.x, v.y);
    p[1] = __floats2half2_rn(v.z, v.w);
}

// ===========================================================================
// One-pass LayerNorm + ReLU, in-place on fp16 (stats in fp32).
// 8 halves (uint4) per thread. 256-thread blocks process multiple rows:
//   H=512: 4 rows/block (64 thr = 2 warps per row)
//   H=256: 8 rows/block (32 thr = 1 warp per row)
// Per-row arithmetic identical to the 1-row version (bit-identical results).
// ===========================================================================
__device__ __forceinline__ float warpSumB(float v) {
    #pragma unroll
    for (int o = 16; o > 0; o >>= 1) v += __shfl_xor_sync(0xffffffffu, v, o);
    return v;
}

template <int H>
__global__ __launch_bounds__(256) void ln_relu_h8(
    __half* __restrict__ x, const float* __restrict__ g,
    const float* __restrict__ be)
{
    constexpr int NT   = H / 8;            // threads per row (64 or 32)
    constexpr int ROWS = 256 / NT;         // rows per block (4 or 8)
    constexpr int NW   = NT / 32;          // warps per row (2 or 1)
    __shared__ float red[2][ROWS][2];      // [stat][row][warp] (used when NW==2)

    const int tid  = threadIdx.x;
    const int rloc = tid / NT;             // row within block
    const int t    = tid % NT;             // thread within row
    const int row  = blockIdx.x * ROWS + rloc;

    uint4* xp = (uint4*)(x + (size_t)row * H);
    uint4 u = xp[t];
    __half2 h0 = *(__half2*)&u.x, h1 = *(__half2*)&u.y;
    __half2 h2 = *(__half2*)&u.z, h3 = *(__half2*)&u.w;
    float2 v0 = __half22float2(h0), v1 = __half22float2(h1);
    float2 v2 = __half22float2(h2), v3 = __half22float2(h3);

    float s  = v0.x + v0.y + v1.x + v1.y + v2.x + v2.y + v3.x + v3.y;
    float s2 = v0.x * v0.x + v0.y * v0.y + v1.x * v1.x + v1.y * v1.y
             + v2.x * v2.x + v2.y * v2.y + v3.x * v3.x + v3.y * v3.y;
    s  = warpSumB(s);
    s2 = warpSumB(s2);
    if constexpr (NW == 2) {
        const int wir = (t >> 5);          // warp within row (0/1)
        if ((t & 31) == 0) { red[0][rloc][wir] = s; red[1][rloc][wir] = s2; }
        __syncthreads();
        s  = red[0][rloc][0] + red[0][rloc][1];
        s2 = red[1][rloc][0] + red[1][rloc][1];
    }
    const float mu  = s / H;
    const float var = s2 / H - mu * mu;
    const float rs  = rsqrtf(var + 1e-5f);

    const float4 g0 = ((const float4*)g)[t * 2];
    const float4 g1 = ((const float4*)g)[t * 2 + 1];
    const float4 b0 = ((const float4*)be)[t * 2];
    const float4 b1 = ((const float4*)be)[t * 2 + 1];

    __half2 o0 = __floats2half2_rn(fmaxf((v0.x - mu) * rs * g0.x + b0.x, 0.f),
                                   fmaxf((v0.y - mu) * rs * g0.y + b0.y, 0.f));
    __half2 o1 = __floats2half2_rn(fmaxf((v1.x - mu) * rs * g0.z + b0.z, 0.f),
                                   fmaxf((v1.y - mu) * rs * g0.w + b0.w, 0.f));
    __half2 o2 = __floats2half2_rn(fmaxf((v2.x - mu) * rs * g1.x + b1.x, 0.f),
                                   fmaxf((v2.y - mu) * rs * g1.y + b1.y, 0.f));
    __half2 o3 = __floats2half2_rn(fmaxf((v3.x - mu) * rs * g1.z + b1.z, 0.f),
                                   fmaxf((v3.y - mu) * rs * g1.w + b1.w, 0.f));
    uint4 o;
    *(__half2*)&o.x = o0; *(__half2*)&o.y = o1;
    *(__half2*)&o.z = o2; *(__half2*)&o.w = o3;
    xp[t] = o;
}

// ===========================================================================
// Warp-per-row epilogue (R13 config: 128 threads = 4 rows/block):
// softmax(fp32 logits) -> attn; W = fp16 wflat * attn; Gram-Schmidt K=4.
// ===========================================================================
__device__ __forceinline__ float warpSum(float v) {
    #pragma unroll
    for (int o = 16; o > 0; o >>= 1) v += __shfl_xor_sync(0xffffffffu, v, o);
    return v;
}
__device__ __forceinline__ float warpMax(float v) {
    #pragma unroll
    for (int o = 16; o > 0; o >>= 1) v = fmaxf(v, __shfl_xor_sync(0xffffffffu, v, o));
    return v;
}

__global__ void epilogue_warp(const __half* __restrict__ wflath,
                              const float* __restrict__ logits,
                              float* __restrict__ out)
{
    const int row  = blockIdx.x * 4 + (threadIdx.x >> 5);
    const int lane = threadIdx.x & 31;
    constexpr int J = Dd / 32;  // 24
    const float* lrow = logits + (size_t)row * Dd;
    const __half* wrow = wflath + (size_t)row * KD;

    float l[J];
    float m = -INFINITY;
    #pragma unroll
    for (int j = 0; j < J; j++) {
        l[j] = lrow[lane + j * 32];
        m = fmaxf(m, l[j]);
    }
    m = warpMax(m);
    float s = 0.f;
    #pragma unroll
    for (int j = 0; j < J; j++) { l[j] = expf(l[j] - m); s += l[j]; }
    s = warpSum(s);
    const float inv_s = 1.f / s;
    float* out_attn = out + (size_t)Bsz * KD;
    #pragma unroll
    for (int j = 0; j < J; j++) {
        l[j] *= inv_s;                       // l[] now holds attn
        out_attn[(size_t)row * Dd + lane + j * 32] = l[j];
    }

    float wv[Kk][J];
    #pragma unroll
    for (int k = 0; k < Kk; k++)
        #pragma unroll
        for (int j = 0; j < J; j++)
            wv[k][j] = __half2float(wrow[k * Dd + lane + j * 32]) * l[j];

    #pragma unroll
    for (int k = 0; k < Kk; k++) {
        #pragma unroll
        for (int p = 0; p < k; p++) {
            float d = 0.f;
            #pragma unroll
            for (int j = 0; j < J; j++) d += wv[k][j] * wv[p][j];
            d = warpSum(d);
            #pragma unroll
            for (int j = 0; j < J; j++) wv[k][j] -= d * wv[p][j];
        }
        float n2 = 0.f;
        #pragma unroll
        for (int j = 0; j < J; j++) n2 += wv[k][j] * wv[k][j];
        n2 = warpSum(n2);
        const float inv = 1.f / fmaxf(sqrtf(n2), 1e-12f);
        #pragma unroll
        for (int j = 0; j < J; j++) {
            wv[k][j] *= inv;
            out[(size_t)row * KD + k * Dd + lane + j * 32] = wv[k][j];
        }
    }
}

// ===========================================================================
extern "C" void kernel_launch(void* const* d_in, const int* in_sizes, int n_in,
                              void* d_out, int out_size)
{
    const float* emb = (const float*)d_in[0];
    const float* W1  = (const float*)d_in[1];
    const float* b1  = (const float*)d_in[2];
    const float* g1  = (const float*)d_in[3];
    const float* be1 = (const float*)d_in[4];
    const float* W2  = (const float*)d_in[5];
    const float* b2  = (const float*)d_in[6];
    const float* g2  = (const float*)d_in[7];
    const float* be2 = (const float*)d_in[8];
    const float* Wd  = (const float*)d_in[9];
    const float* bd  = (const float*)d_in[10];
    const float* Wa  = (const float*)d_in[11];
    const float* ba  = (const float*)d_in[12];
    float* out = (float*)d_out;

    float *logits;
    __half *wflath, *embh, *h1h, *h2h, *W1h, *W2h, *Wch;
    cudaGetSymbolAddress((void**)&logits, g_logits);
    cudaGetSymbolAddress((void**)&wflath, g_wflath);
    cudaGetSymbolAddress((void**)&embh, g_embh);
    cudaGetSymbolAddress((void**)&h1h, g_h1h);
    cudaGetSymbolAddress((void**)&h2h, g_h2h);
    cudaGetSymbolAddress((void**)&W1h, g_W1h);
    cudaGetSymbolAddress((void**)&W2h, g_W2h);
    cudaGetSymbolAddress((void**)&Wch, g_Wch);

    cudaFuncSetAttribute((const void*)mma_gemm<false>,
                         cudaFuncAttributeMaxDynamicSharedMemorySize, GEMM_SMEM_BYTES);
    cudaFuncSetAttribute((const void*)mma_gemm<true>,
                         cudaFuncAttributeMaxDynamicSharedMemorySize, GEMM_SMEM_BYTES);

    // Converts: emb + W1 + W2 in one kernel; Wd + Wa -> Wch in one kernel
    {
        int n0 = Bsz * Dd, n1 = Dd * H1, n2 = H1 * H2;
        int q = (n0 + n1 + n2) / 4;
        cvt3_k<<<(q + 255) / 256, 256>>>(emb, embh, n0, W1, W1h, n1, W2, W2h, n2);
    }
    {
        int q = (H2 * KD + H2 * Dd) / 4;
        cvt_wch_k<<<(q + 255) / 256, 256>>>(Wd, Wa, Wch);
    }

    // Layer 1 (R13 config): fp16 out, LN in-place (4 rows per 256-thr block)
    mma_gemm<false><<<dim3(H1 / BN, Bsz / BM), 256, GEMM_SMEM_BYTES>>>(
        embh, W1h, b1, h1h, nullptr, nullptr, nullptr, Bsz, H1, Dd);
    ln_relu_h8<H1><<<Bsz / (256 / (H1 / 8)), 256>>>(h1h, g1, be1);
    // Layer 2 (8 rows per 256-thr block)
    mma_gemm<false><<<dim3(H2 / BN, Bsz / BM), 256, GEMM_SMEM_BYTES>>>(
        h1h, W2h, b2, h2h, nullptr, nullptr, nullptr, Bsz, H2, H1);
    ln_relu_h8<H2><<<Bsz / (256 / (H2 / 8)), 256>>>(h2h, g2, be2);
    // Merged heads with mixed store: wflat -> fp16, logits -> fp32
    mma_gemm<true><<<dim3(NC / BN, Bsz / BM), 256, GEMM_SMEM_BYTES>>>(
        h2h, Wch, bd, nullptr, ba, wflath, logits, Bsz, NC, H2);
    // softmax + modulate + Gram-Schmidt (warp per row, 4 rows/block)
    epilogue_warp<<<Bsz / 4, 128>>>(wflath, logits, out);
}